// round 13
// baseline (speedup 1.0000x reference)
#include <cuda_runtime.h>
#include <cuda_bf16.h>
#include <cstddef>

// score(f) = 1 + tanh(f.W + b)/10 ; e[parent] = score(c0)*e[c0] + score(c1)*e[c1]
// Complete binary tree, level order, D=21, N = 2^21 - 1, F = 64.
// Phase A: flat pass over ALL 16-row tiles, each warp owns a private
//          3-stage cp.async ring in smem (no block syncs, no data registers
//          held across iterations). Internal rows -> g_scores; leaf rows ->
//          level-19 parents directly.
// Phase B: levels 19..12 as tiny score-lookup passes; 11..1 on block 0.

#define TANH_INV_SCALAR 0.1f
#define NB       296        // 2 blocks/SM on 148 SMs -> all resident
#define NT       256
#define WPB      (NT / 32)
#define NWARPS   (NB * WPB)
#define NTH      (NB * NT)

#define DEPTH        3
#define TILE_FLOATS  1024                    // 16 rows * 64 floats = 4KB
#define RING_FLOATS  (DEPTH * TILE_FLOATS)
#define SMEM_FLOATS  (WPB * RING_FLOATS)
#define SMEM_BYTES   (SMEM_FLOATS * 4)       // 98,304 B

#define LEAF_START ((1 << 20) - 1)
#define N_INT_TILES (1 << 16)
#define N_TILES     (1 << 17)

__device__ float g_scores[1 << 20];
__device__ unsigned g_count = 0;
__device__ volatile unsigned g_gen = 0;

__device__ __forceinline__ void grid_barrier()
{
    __syncthreads();
    if (threadIdx.x == 0) {
        __threadfence();
        unsigned g = g_gen;
        if (atomicAdd(&g_count, 1u) == NB - 1u) {
            g_count = 0;
            __threadfence();
            g_gen = g + 1u;
        } else {
            while (g_gen == g) { __nanosleep(32); }
            __threadfence();
        }
    }
    __syncthreads();
}

__device__ __forceinline__ float tanh_fast(float x)
{
    float y;
    asm("tanh.approx.f32 %0, %1;" : "=f"(y) : "f"(x));
    return y;
}

__device__ __forceinline__ int tile_base(int T)
{
    return (T < N_INT_TILES) ? (T << 4)
                             : LEAF_START + ((T - N_INT_TILES) << 4);
}

// Issue one tile's 8 cp.asyncs (16B per lane each) into a ring stage and
// commit. Out-of-range tiles commit an empty group to keep counts aligned.
__device__ __forceinline__ void stage_issue(unsigned stage_saddr,
                                            const float* __restrict__ features,
                                            int T, int lane)
{
    if (T < N_TILES) {
        const char* g = reinterpret_cast<const char*>(
            features + (size_t)tile_base(T) * 64);
        #pragma unroll
        for (int j = 0; j < 8; ++j) {
            unsigned off = (unsigned)((j * 32 + lane) * 16);
            asm volatile("cp.async.cg.shared.global [%0], [%1], 16;"
                         :: "r"(stage_saddr + off), "l"(g + off));
        }
    }
    asm volatile("cp.async.commit_group;" ::: "memory");
}

__global__ void __launch_bounds__(NT, 2)
tree_all_kernel(const float* __restrict__ features,
                const float* __restrict__ leaf_energy,
                const float* __restrict__ W,
                const float* __restrict__ bptr,
                float* __restrict__ energy)
{
    extern __shared__ float sm[];
    const int tid   = threadIdx.x;
    const int lane  = tid & 31;
    const int warp  = tid >> 5;
    const int gtid  = blockIdx.x * NT + tid;
    const int gwarp = gtid >> 5;

    const float4 wv = reinterpret_cast<const float4*>(W)[lane & 15];
    const float  b  = __ldg(bptr);

    const bool s3 = lane & 8, s2 = lane & 4, s1 = lane & 2;
    const int  h  = lane >> 4;
    const int  vi = ((lane >> 3) & 1) | (((lane >> 2) & 1) << 1)
                  | (((lane >> 1) & 1) << 2);
    const int  rr = 2 * vi + h;

    // Warp-private ring base (shared-space address for cp.async).
    const unsigned ring_saddr = (unsigned)__cvta_generic_to_shared(
        sm + warp * RING_FLOATS);
    const float* ring = sm + warp * RING_FLOATS;

    // ================= Phase A: flat scoring pass, cp.async ring ============
    {
        // Prologue: fill DEPTH-1 stages.
        stage_issue(ring_saddr + 0 * TILE_FLOATS * 4, features,
                    gwarp + 0 * NWARPS, lane);
        stage_issue(ring_saddr + 1 * TILE_FLOATS * 4, features,
                    gwarp + 1 * NWARPS, lane);

        int s_cons = 0, s_issue = 2;
        for (int T = gwarp; T < N_TILES; T += NWARPS) {
            // Keep the ring full: issue T + (DEPTH-1)*NWARPS.
            stage_issue(ring_saddr + (unsigned)s_issue * TILE_FLOATS * 4,
                        features, T + (DEPTH - 1) * NWARPS, lane);
            s_issue = (s_issue + 1) % DEPTH;

            // Leaf-energy prefetch (register load, independent).
            const int  cb      = tile_base(T);
            const bool is_leaf = (T >= N_INT_TILES);
            float e = 0.0f;
            if (is_leaf)
                e = __ldg(&leaf_energy[cb + rr - LEAF_START]);

            // Wait for T's stage only (2 iterations after its issue).
            asm volatile("cp.async.wait_group %0;" :: "n"(DEPTH - 1) : "memory");

            // Convert from smem: 8 LDS.128 + dot4 each.
            const float* st = ring + s_cons * TILE_FLOATS;
            s_cons = (s_cons + 1) % DEPTH;
            float part[8];
            #pragma unroll
            for (int j = 0; j < 8; ++j) {
                float4 f = *reinterpret_cast<const float4*>(
                    st + (j * 32 + lane) * 4);
                part[j] = f.x * wv.x + f.y * wv.y + f.z * wv.z + f.w * wv.w;
            }

            // Folding butterfly: every lane ends with full dot of row rr.
            float a4[4];
            #pragma unroll
            for (int j = 0; j < 4; ++j) {
                float u0 = part[2*j]   + __shfl_xor_sync(~0u, part[2*j],   8);
                float u1 = part[2*j+1] + __shfl_xor_sync(~0u, part[2*j+1], 8);
                a4[j] = s3 ? u1 : u0;
            }
            float a2[2];
            #pragma unroll
            for (int j = 0; j < 2; ++j) {
                float u0 = a4[2*j]   + __shfl_xor_sync(~0u, a4[2*j],   4);
                float u1 = a4[2*j+1] + __shfl_xor_sync(~0u, a4[2*j+1], 4);
                a2[j] = s2 ? u1 : u0;
            }
            float u0 = a2[0] + __shfl_xor_sync(~0u, a2[0], 2);
            float u1 = a2[1] + __shfl_xor_sync(~0u, a2[1], 2);
            float a1 = s1 ? u1 : u0;
            float dot = a1 + __shfl_xor_sync(~0u, a1, 1);

            float sc = 1.0f + tanh_fast(dot + b) * TANH_INV_SCALAR;

            if (!is_leaf) {
                if ((lane & 1) == 0 && cb + rr < LEAF_START)
                    __stcg(&g_scores[cb + rr], sc);
            } else {
                if ((lane & 1) == 0)
                    __stcg(&energy[cb + rr], e);          // seed output leaves
                float contrib = sc * e;
                float other = __shfl_xor_sync(~0u, contrib, 16);
                if (h == 0 && (lane & 1) == 0) {
                    const int t = T - N_INT_TILES;
                    __stcg(&energy[(1 << 19) - 1 + 8 * t + vi],
                           contrib + other);              // level-19 parents
                }
            }
        }
        asm volatile("cp.async.wait_group 0;" ::: "memory");
    }
    grid_barrier();

    // ================= Phase B: levels d = 19 .. 12 (score lookups) =========
    for (int d = 19; d >= 12; --d) {
        const int np     = 1 << (d - 1);
        const int pstart = np - 1;
        for (int i = gtid; i < np; i += NTH) {
            const int p = pstart + i;
            const int c = 2 * p + 1;
            float sc0 = __ldcg(&g_scores[c]);
            float sc1 = __ldcg(&g_scores[c + 1]);
            float e0 = __ldcg(&energy[c]);
            float e1 = __ldcg(&energy[c + 1]);
            __stcg(&energy[p], sc0 * e0 + sc1 * e1);
        }
        grid_barrier();
    }

    // ================= Tail: levels d = 11 .. 1 on block 0 ==================
    if (blockIdx.x != 0) return;
    for (int d = 11; d >= 1; --d) {
        const int np     = 1 << (d - 1);
        const int pstart = np - 1;
        for (int i = tid; i < np; i += NT) {
            const int p = pstart + i;
            const int c = 2 * p + 1;
            float sc0 = __ldcg(&g_scores[c]);
            float sc1 = __ldcg(&g_scores[c + 1]);
            float e0 = __ldcg(&energy[c]);
            float e1 = __ldcg(&energy[c + 1]);
            __stcg(&energy[p], sc0 * e0 + sc1 * e1);
        }
        __syncthreads();
    }
}

extern "C" void kernel_launch(void* const* d_in, const int* in_sizes, int n_in,
                              void* d_out, int out_size)
{
    const float* features    = (const float*)d_in[0];   // [N, 64]
    const float* leaf_energy = (const float*)d_in[1];   // [2^20]
    const float* W           = (const float*)d_in[2];   // [64]
    const float* bptr        = (const float*)d_in[3];   // [1]
    float* energy = (float*)d_out;                      // [N]

    cudaFuncSetAttribute(tree_all_kernel,
                         cudaFuncAttributeMaxDynamicSharedMemorySize, SMEM_BYTES);
    tree_all_kernel<<<NB, NT, SMEM_BYTES>>>(features, leaf_energy, W, bptr, energy);
}